// round 15
// baseline (speedup 1.0000x reference)
#include <cuda_runtime.h>
#include <math.h>

#define SRC 2      // 0 = lab, 1 = pred-argmax
#define NB  4
#define NC  3
#define HH  256
#define WW  256
#define NPIX (HH*WW)
#define LIMIT_F 331776.0f   // 576*576
#define NORM_EPS 1e-5f
#define DINF (1 << 20)

// Scratch (device globals). Big arrays TRANSPOSED: [src][b][j][i]
// g_dmT: row-pass distance to nearest different-label pixel in the row,
//        1..255, or 0 == "none in row" (reference BIG). r2 = dm ? dm^2 : 1e9 exactly.
__device__ unsigned char g_lblT[SRC][NB][WW][HH];
__device__ unsigned char g_dmT [SRC][NB][WW][HH];
__device__ float         g_edtT[SRC][NB][WW][HH];
__device__ unsigned int  g_cmax[SRC][NB][NC];
__device__ float         g_lossb[NB];     // per-batch sim sum
__device__ int           g_fgc[NB];       // per-batch fg count
__device__ unsigned int  g_bcnt[NB];      // per-batch k2-block arrival count (reset by finisher)
__device__ unsigned int  g_tick;          // finisher count (reset by combiner)

// ---------------------------------------------------------------------------
// K1: fused argmax + label pack + ballot row-pass EDT. One block = 4 rows.
// (Measured-best configuration; unchanged.)
__global__ void __launch_bounds__(256) k1(const float* __restrict__ pred,
                                          const int* __restrict__ lab) {
    int bx = blockIdx.x;            // 0..255
    int b  = bx >> 6;
    int i0 = (bx & 63) << 2;
    int t  = threadIdx.x;
    if (bx == 0 && t < SRC*NB*NC) ((unsigned int*)g_cmax)[t] = 0u;

    __shared__ unsigned char s_lb[SRC][4][WW];
    __shared__ unsigned char s_dm[SRC][4][WW];
    __shared__ int           s_last[8][8], s_first[8][8];  // [comb][warp]

    // Phase A: vectorized loads + argmax. thread t -> row r, cols jj..jj+3
    {
        int r  = t >> 6;
        int jj = (t & 63) << 2;
        size_t off = (size_t)b * NC * NPIX + (size_t)(i0 + r) * WW + jj;
        float4 p0 = *(const float4*)(pred + off);
        float4 p1 = *(const float4*)(pred + off + NPIX);
        float4 p2 = *(const float4*)(pred + off + 2*NPIX);
        int4   lv = *(const int4*)(lab + (size_t)b * NPIX + (size_t)(i0 + r) * WW + jj);
        uchar4 am;
        { int a=0; float v=p0.x; if (p1.x>v){v=p1.x;a=1;} if (p2.x>v){a=2;} am.x=(unsigned char)a; }
        { int a=0; float v=p0.y; if (p1.y>v){v=p1.y;a=1;} if (p2.y>v){a=2;} am.y=(unsigned char)a; }
        { int a=0; float v=p0.z; if (p1.z>v){v=p1.z;a=1;} if (p2.z>v){a=2;} am.z=(unsigned char)a; }
        { int a=0; float v=p0.w; if (p1.w>v){v=p1.w;a=1;} if (p2.w>v){a=2;} am.w=(unsigned char)a; }
        *(uchar4*)&s_lb[1][r][jj] = am;
        *(uchar4*)&s_lb[0][r][jj] = make_uchar4((unsigned char)lv.x, (unsigned char)lv.y,
                                                (unsigned char)lv.z, (unsigned char)lv.w);
    }
    __syncthreads();

    // Phase B: ballot boundary detection; thread j, 8 (src,row) combos.
    int j = t, lane = j & 31, w = j >> 5, base = j & ~31;
    unsigned mask_le = 0xffffffffu >> (31 - lane);
    int dl[8], dr[8];
    #pragma unroll
    for (int c = 0; c < 8; ++c) {
        const unsigned char* L = s_lb[c >> 2][c & 3];
        int bit = (j > 0) && (L[j] != L[j - 1]);
        unsigned bb = __ballot_sync(0xffffffffu, bit);
        unsigned bl = bb & mask_le;
        unsigned br = bb & ~mask_le;
        dl[c] = bl ? (lane - (31 - __clz(bl)) + 1) : DINF;
        dr[c] = br ? ((__ffs(br) - 1) - lane) : DINF;
        if (lane == 0) {
            s_last [c][w] = bb ? (base + 31 - __clz(bb)) : -1;
            s_first[c][w] = bb ? (base + __ffs(bb) - 1)  : -1;
        }
    }
    __syncthreads();

    // Phase C: cross-warp fallback (rare) + write dm byte (0 = sentinel).
    #pragma unroll
    for (int c = 0; c < 8; ++c) {
        if (dl[c] == DINF)
            for (int w2 = w - 1; w2 >= 0; --w2) {
                int k = s_last[c][w2];
                if (k >= 0) { dl[c] = j - k + 1; break; }
            }
        if (dr[c] == DINF)
            for (int w2 = w + 1; w2 < 8; ++w2) {
                int k = s_first[c][w2];
                if (k >= 0) { dr[c] = k - j; break; }
            }
        int dm = min(dl[c], dr[c]);          // <=255 when found (row width 256)
        s_dm[c >> 2][c & 3][j] = (unsigned char)((dm <= 255) ? dm : 0);
    }
    __syncthreads();

    // Phase D: transposed uchar4 stores (4 rows per column), 8B per source.
    #pragma unroll
    for (int s = 0; s < SRC; ++s) {
        *(uchar4*)&g_lblT[s][b][j][i0] =
            make_uchar4(s_lb[s][0][j], s_lb[s][1][j], s_lb[s][2][j], s_lb[s][3][j]);
        *(uchar4*)&g_dmT[s][b][j][i0] =
            make_uchar4(s_dm[s][0][j], s_dm[s][1][j], s_dm[s][2][j], s_dm[s][3][j]);
    }
}

// ---------------------------------------------------------------------------
// K2F: column pass (512 blocks; proven body) + ticketed tail-fusion:
// the LAST k2 block of each batch (128 per batch) immediately reduces that
// batch's cosine-sim; the 4th batch-finisher combines the scalar loss.
// No block ever waits — non-finishers exit at once.
__global__ void __launch_bounds__(256) k2f(float* __restrict__ out) {
    int bx = blockIdx.x;            // 0..511
    int s  = bx >> 8;
    int b  = (bx >> 6) & 3;
    int j0 = (bx & 63) << 2;
    int i  = threadIdx.x;

    __shared__ unsigned char s_lb2[4][HH];
    __shared__ float         s_rd2[4][HH];
    __shared__ int           s_last[4][8], s_first[4][8];
    __shared__ unsigned int  smax[NC];
    __shared__ int           s_fin;
    if (i < NC) smax[i] = 0u;
    #pragma unroll
    for (int q = 0; q < 4; ++q) {
        s_lb2[q][i] = g_lblT[s][b][j0 + q][i];
        unsigned char dv = g_dmT[s][b][j0 + q][i];
        s_rd2[q][i] = dv ? (float)((int)dv * (int)dv) : 1e9f;   // exact reconstruction
    }
    __syncthreads();

    int lane = i & 31, w = i >> 5, base = i & ~31;
    unsigned mask_le = 0xffffffffu >> (31 - lane);
    int dl[4], dr[4];
    #pragma unroll
    for (int q = 0; q < 4; ++q) {
        const unsigned char* L = s_lb2[q];
        int bit = (i > 0) && (L[i] != L[i - 1]);
        unsigned bb = __ballot_sync(0xffffffffu, bit);
        unsigned bl = bb & mask_le;
        unsigned br = bb & ~mask_le;
        dl[q] = bl ? (lane - (31 - __clz(bl)) + 1) : DINF;
        dr[q] = br ? ((__ffs(br) - 1) - lane) : DINF;
        if (lane == 0) {
            s_last [q][w] = bb ? (base + 31 - __clz(bb)) : -1;
            s_first[q][w] = bb ? (base + __ffs(bb) - 1)  : -1;
        }
    }
    __syncthreads();

    #pragma unroll
    for (int q = 0; q < 4; ++q) {
        if (dl[q] == DINF)
            for (int w2 = w - 1; w2 >= 0; --w2) {
                int k = s_last[q][w2];
                if (k >= 0) { dl[q] = i - k + 1; break; }
            }
        if (dr[q] == DINF)
            for (int w2 = w + 1; w2 < 8; ++w2) {
                int k = s_first[q][w2];
                if (k >= 0) { dr[q] = k - i; break; }
            }
        const float* R = s_rd2[q];
        float best = R[i];
        int dm = min(dl[q], dr[q]);
        if (dm < DINF) best = fminf(best, (float)(dm * dm));  // nearest different px, f=0
        // Exact interior scan: only same-run pixels (d < dl/dr) can win; past the
        // first different pixel every candidate has qd >= dl^2 >= best.
        int lim = min(dl[q], i + 1);
        for (int d = 1; d < lim; ++d) {
            float qd = (float)(d * d);
            if (qd >= best) break;
            float v = R[i - d] + qd;
            if (v < best) best = v;
        }
        lim = min(dr[q], HH - i);
        for (int d = 1; d < lim; ++d) {
            float qd = (float)(d * d);
            if (qd >= best) break;
            float v = R[i + d] + qd;
            if (v < best) best = v;
        }
        float e = sqrtf(best);
        g_edtT[s][b][j0 + q][i] = e;
        atomicMax(&smax[s_lb2[q][i]], __float_as_uint(e));  // e>=0: uint order == float
    }
    __syncthreads();
    if (i < NC) atomicMax(&g_cmax[s][b][i], smax[i]);
    __syncthreads();

    // ---- per-batch ticket: last of this batch's 128 blocks runs the reduce ----
    if (i == 0) {
        __threadfence();                                 // release this block's writes
        unsigned old = atomicAdd(&g_bcnt[b], 1u);
        s_fin = (old == 127u);
    }
    __syncthreads();
    if (!s_fin) return;

    __threadfence();                                     // acquire all batch writes

    // ---- batch-b cosine-sim reduce (was K3): 65536 px over 256 threads ----
    __shared__ float s_invl[NC], s_invp[NC];
    __shared__ float wsum[8];
    __shared__ int   wfg[8];
    if (i < NC)
        s_invl[i] = 1.0f / (fminf(__uint_as_float(g_cmax[0][b][i]), LIMIT_F) + NORM_EPS);
    else if (i < 2*NC)
        s_invp[i - NC] = 1.0f / (fminf(__uint_as_float(g_cmax[1][b][i - NC]), LIMIT_F) + NORM_EPS);
    __syncthreads();

    const uchar4* Lc = (const uchar4*)g_lblT[0][b];
    const uchar4* Pc = (const uchar4*)g_lblT[1][b];
    const float4* Le = (const float4*)g_edtT[0][b];
    const float4* Pe = (const float4*)g_edtT[1][b];

    float acc = 0.0f; int fg = 0;
    #pragma unroll 4
    for (int u = 0; u < 64; ++u) {                       // 64 float4-groups per thread
        int v = u * 256 + i;
        uchar4 lc = Lc[v], pc = Pc[v];
        float4 le = Le[v], pe = Pe[v];
        {
            float sl = le.x * s_invl[lc.x], sp = pe.x * s_invp[pc.x];
            float dot = sp * sl + ((lc.x == pc.x) ? 1.0f : 0.0f);
            acc += dot * rsqrtf((sp * sp + 1.0f) * (sl * sl + 1.0f));
            fg += (lc.x > 0);
        }
        {
            float sl = le.y * s_invl[lc.y], sp = pe.y * s_invp[pc.y];
            float dot = sp * sl + ((lc.y == pc.y) ? 1.0f : 0.0f);
            acc += dot * rsqrtf((sp * sp + 1.0f) * (sl * sl + 1.0f));
            fg += (lc.y > 0);
        }
        {
            float sl = le.z * s_invl[lc.z], sp = pe.z * s_invp[pc.z];
            float dot = sp * sl + ((lc.z == pc.z) ? 1.0f : 0.0f);
            acc += dot * rsqrtf((sp * sp + 1.0f) * (sl * sl + 1.0f));
            fg += (lc.z > 0);
        }
        {
            float sl = le.w * s_invl[lc.w], sp = pe.w * s_invp[pc.w];
            float dot = sp * sl + ((lc.w == pc.w) ? 1.0f : 0.0f);
            acc += dot * rsqrtf((sp * sp + 1.0f) * (sl * sl + 1.0f));
            fg += (lc.w > 0);
        }
    }

    #pragma unroll
    for (int o = 16; o > 0; o >>= 1) {
        acc += __shfl_down_sync(0xffffffffu, acc, o);
        fg  += __shfl_down_sync(0xffffffffu, fg,  o);
    }
    int ww = i >> 5;
    if ((i & 31) == 0) { wsum[ww] = acc; wfg[ww] = fg; }
    __syncthreads();

    if (i == 0) {
        float ssum = 0.0f; int sf = 0;
        #pragma unroll
        for (int k = 0; k < 8; ++k) { ssum += wsum[k]; sf += wfg[k]; }
        g_lossb[b] = ssum;
        g_fgc[b]   = sf;
        g_bcnt[b]  = 0u;                   // reset for next graph replay
        __threadfence();                   // release loss_b
        unsigned old = atomicAdd(&g_tick, 1u);
        if (old == NB - 1u) {              // 4th batch finisher combines
            __threadfence();               // acquire other batches' loss_b
            double loss = 0.0;
            for (int bb = 0; bb < NB; ++bb) {
                float lb2 = 1.0f - (float)((double)g_lossb[bb] / 65536.0);
                if (g_fgc[bb] > 0) loss += (double)lb2;
            }
            float L = (float)(loss / (double)NB);
            if (isnan(L)) L = 0.0f;
            else if (isinf(L)) L = (L > 0.0f) ? 1.0f : 0.0f;
            out[0] = L;
            g_tick = 0u;                   // reset for next graph replay
        }
    }
}

// ---------------------------------------------------------------------------
extern "C" void kernel_launch(void* const* d_in, const int* in_sizes, int n_in,
                              void* d_out, int out_size) {
    const float* pred;
    const int*   lab;
    if (n_in >= 2 && in_sizes[0] == NB*NPIX && in_sizes[1] == NB*NC*NPIX) {
        lab  = (const int*)d_in[0];
        pred = (const float*)d_in[1];
    } else {
        pred = (const float*)d_in[0];
        lab  = (const int*)d_in[1];
    }
    float* out = (float*)d_out;

    k1<<<NB*HH/4, 256>>>(pred, lab);      // 256 blocks — measured optimum
    k2f<<<SRC*NB*WW/4, 256>>>(out);       // 512 blocks; ticketed tail-fused finish
    (void)out_size;
}

// round 16
// speedup vs baseline: 1.9576x; 1.9576x over previous
#include <cuda_runtime.h>
#include <math.h>

#define SRC 2      // 0 = lab, 1 = pred-argmax
#define NB  4
#define NC  3
#define HH  256
#define WW  256
#define NPIX (HH*WW)
#define LIMIT_F 331776.0f   // 576*576
#define NORM_EPS 1e-5f
#define DINF (1 << 20)

// Scratch (device globals). Transposed arrays: [src][b][j][i]
// g_pkT: (dm << 2) | label. dm = row-distance to nearest different-label pixel,
//        1..255, or 0 == "none in row" (reference BIG). rd = dm ? dm^2 : 1e9 exactly.
__device__ unsigned short g_pkT [SRC][NB][WW][HH];
__device__ float          g_edtT[SRC][NB][WW][HH];
__device__ unsigned int   g_cmax[SRC][NB][NC];
__device__ float          g_psum[NB][16];
__device__ int            g_pfg [NB][16];
__device__ unsigned int   g_tick;   // zero-init; reset by last K3 block

// ---------------------------------------------------------------------------
// K1: fused argmax + label pack + ballot row-pass EDT. One block = 4 rows.
// (Measured-best grid: 256 blocks x 256 threads.)
__global__ void __launch_bounds__(256) k1(const float* __restrict__ pred,
                                          const int* __restrict__ lab) {
    int bx = blockIdx.x;            // 0..255
    int b  = bx >> 6;
    int i0 = (bx & 63) << 2;
    int t  = threadIdx.x;
    if (bx == 0 && t < SRC*NB*NC) ((unsigned int*)g_cmax)[t] = 0u;

    __shared__ unsigned char  s_lb[SRC][4][WW];
    __shared__ unsigned short s_pk[SRC][4][WW];
    __shared__ int            s_last[8][8], s_first[8][8];  // [comb][warp]

    // Phase A: vectorized loads + argmax. thread t -> row r, cols jj..jj+3
    {
        int r  = t >> 6;
        int jj = (t & 63) << 2;
        size_t off = (size_t)b * NC * NPIX + (size_t)(i0 + r) * WW + jj;
        float4 p0 = *(const float4*)(pred + off);
        float4 p1 = *(const float4*)(pred + off + NPIX);
        float4 p2 = *(const float4*)(pred + off + 2*NPIX);
        int4   lv = *(const int4*)(lab + (size_t)b * NPIX + (size_t)(i0 + r) * WW + jj);
        uchar4 am;
        { int a=0; float v=p0.x; if (p1.x>v){v=p1.x;a=1;} if (p2.x>v){a=2;} am.x=(unsigned char)a; }
        { int a=0; float v=p0.y; if (p1.y>v){v=p1.y;a=1;} if (p2.y>v){a=2;} am.y=(unsigned char)a; }
        { int a=0; float v=p0.z; if (p1.z>v){v=p1.z;a=1;} if (p2.z>v){a=2;} am.z=(unsigned char)a; }
        { int a=0; float v=p0.w; if (p1.w>v){v=p1.w;a=1;} if (p2.w>v){a=2;} am.w=(unsigned char)a; }
        *(uchar4*)&s_lb[1][r][jj] = am;
        *(uchar4*)&s_lb[0][r][jj] = make_uchar4((unsigned char)lv.x, (unsigned char)lv.y,
                                                (unsigned char)lv.z, (unsigned char)lv.w);
    }
    __syncthreads();

    // Phase B: ballot boundary detection; thread j, 8 (src,row) combos.
    int j = t, lane = j & 31, w = j >> 5, base = j & ~31;
    unsigned mask_le = 0xffffffffu >> (31 - lane);
    int dl[8], dr[8];
    #pragma unroll
    for (int c = 0; c < 8; ++c) {
        const unsigned char* L = s_lb[c >> 2][c & 3];
        int bit = (j > 0) && (L[j] != L[j - 1]);
        unsigned bb = __ballot_sync(0xffffffffu, bit);
        unsigned bl = bb & mask_le;
        unsigned br = bb & ~mask_le;
        dl[c] = bl ? (lane - (31 - __clz(bl)) + 1) : DINF;
        dr[c] = br ? ((__ffs(br) - 1) - lane) : DINF;
        if (lane == 0) {
            s_last [c][w] = bb ? (base + 31 - __clz(bb)) : -1;
            s_first[c][w] = bb ? (base + __ffs(bb) - 1)  : -1;
        }
    }
    __syncthreads();

    // Phase C: cross-warp fallback (rare) + write packed (dm<<2)|lbl.
    #pragma unroll
    for (int c = 0; c < 8; ++c) {
        if (dl[c] == DINF)
            for (int w2 = w - 1; w2 >= 0; --w2) {
                int k = s_last[c][w2];
                if (k >= 0) { dl[c] = j - k + 1; break; }
            }
        if (dr[c] == DINF)
            for (int w2 = w + 1; w2 < 8; ++w2) {
                int k = s_first[c][w2];
                if (k >= 0) { dr[c] = k - j; break; }
            }
        int dm = min(dl[c], dr[c]);          // <=255 when found (row width 256)
        if (dm > 255) dm = 0;                // 0 == sentinel (no boundary in row)
        s_pk[c >> 2][c & 3][j] =
            (unsigned short)((dm << 2) | s_lb[c >> 2][c & 3][j]);
    }
    __syncthreads();

    // Phase D: transposed ushort4 stores — ONE 8B store per source per thread.
    #pragma unroll
    for (int s = 0; s < SRC; ++s) {
        *(ushort4*)&g_pkT[s][b][j][i0] =
            make_ushort4(s_pk[s][0][j], s_pk[s][1][j], s_pk[s][2][j], s_pk[s][3][j]);
    }
}

// ---------------------------------------------------------------------------
// K2: column pass = ballot boundary init + bounded exact interior scan.
// Measured-best grid: 512 blocks x 256 threads, 4 columns per block.
__global__ void __launch_bounds__(256) k2() {
    int bx = blockIdx.x;            // 0..511
    int s  = bx >> 8;
    int b  = (bx >> 6) & 3;
    int j0 = (bx & 63) << 2;
    int i  = threadIdx.x;

    __shared__ unsigned char s_lb2[4][HH];
    __shared__ float         s_rd2[4][HH];
    __shared__ int           s_last[4][8], s_first[4][8];
    __shared__ unsigned int  smax[NC];
    if (i < NC) smax[i] = 0u;
    #pragma unroll
    for (int q = 0; q < 4; ++q) {
        unsigned short p = g_pkT[s][b][j0 + q][i];
        int dm = p >> 2;
        s_lb2[q][i] = (unsigned char)(p & 3);
        s_rd2[q][i] = dm ? (float)(dm * dm) : 1e9f;   // exact reconstruction
    }
    __syncthreads();

    int lane = i & 31, w = i >> 5, base = i & ~31;
    unsigned mask_le = 0xffffffffu >> (31 - lane);
    int dl[4], dr[4];
    #pragma unroll
    for (int q = 0; q < 4; ++q) {
        const unsigned char* L = s_lb2[q];
        int bit = (i > 0) && (L[i] != L[i - 1]);
        unsigned bb = __ballot_sync(0xffffffffu, bit);
        unsigned bl = bb & mask_le;
        unsigned br = bb & ~mask_le;
        dl[q] = bl ? (lane - (31 - __clz(bl)) + 1) : DINF;
        dr[q] = br ? ((__ffs(br) - 1) - lane) : DINF;
        if (lane == 0) {
            s_last [q][w] = bb ? (base + 31 - __clz(bb)) : -1;
            s_first[q][w] = bb ? (base + __ffs(bb) - 1)  : -1;
        }
    }
    __syncthreads();

    #pragma unroll
    for (int q = 0; q < 4; ++q) {
        if (dl[q] == DINF)
            for (int w2 = w - 1; w2 >= 0; --w2) {
                int k = s_last[q][w2];
                if (k >= 0) { dl[q] = i - k + 1; break; }
            }
        if (dr[q] == DINF)
            for (int w2 = w + 1; w2 < 8; ++w2) {
                int k = s_first[q][w2];
                if (k >= 0) { dr[q] = k - i; break; }
            }
        const float* R = s_rd2[q];
        float best = R[i];
        int dm = min(dl[q], dr[q]);
        if (dm < DINF) best = fminf(best, (float)(dm * dm));  // nearest different px, f=0
        // Exact interior scan: only same-run pixels (d < dl/dr) can win; past the
        // first different pixel every candidate has qd >= dl^2 >= best.
        int lim = min(dl[q], i + 1);
        for (int d = 1; d < lim; ++d) {
            float qd = (float)(d * d);
            if (qd >= best) break;
            float v = R[i - d] + qd;
            if (v < best) best = v;
        }
        lim = min(dr[q], HH - i);
        for (int d = 1; d < lim; ++d) {
            float qd = (float)(d * d);
            if (qd >= best) break;
            float v = R[i + d] + qd;
            if (v < best) best = v;
        }
        float e = sqrtf(best);
        g_edtT[s][b][j0 + q][i] = e;
        atomicMax(&smax[s_lb2[q][i]], __float_as_uint(e));  // e>=0: uint order == float
    }
    __syncthreads();
    if (i < NC) atomicMax(&g_cmax[s][b][i], smax[i]);
}

// ---------------------------------------------------------------------------
// K3: per-pixel cosine similarity + deterministic reduce + ticketed finish.
// 64 blocks (spread matters: MUFU rsqrt throughput — see R15 post-mortem).
__global__ void __launch_bounds__(256) k3(float* __restrict__ out) {
    int b = blockIdx.y;
    int t = threadIdx.x;
    __shared__ float s_invl[NC], s_invp[NC];
    __shared__ float wsum[8];
    __shared__ int   wfg[8];
    if (t < NC)
        s_invl[t] = 1.0f / (fminf(__uint_as_float(g_cmax[0][b][t]), LIMIT_F) + NORM_EPS);
    else if (t < 2*NC)
        s_invp[t - NC] = 1.0f / (fminf(__uint_as_float(g_cmax[1][b][t - NC]), LIMIT_F) + NORM_EPS);
    __syncthreads();

    const ushort4* Lc = (const ushort4*)g_pkT[0][b];
    const ushort4* Pc = (const ushort4*)g_pkT[1][b];
    const float4*  Le = (const float4*)g_edtT[0][b];
    const float4*  Pe = (const float4*)g_edtT[1][b];

    int base = blockIdx.x * 1024;
    float acc = 0.0f; int fg = 0;
    #pragma unroll
    for (int u = 0; u < 4; ++u) {
        int v = base + u * 256 + t;
        ushort4 lc = Lc[v], pc = Pc[v];
        float4  le = Le[v], pe = Pe[v];
        {
            int cl = lc.x & 3, cp = pc.x & 3;
            float sl = le.x * s_invl[cl], sp = pe.x * s_invp[cp];
            float dot = sp * sl + ((cl == cp) ? 1.0f : 0.0f);
            acc += dot * rsqrtf((sp * sp + 1.0f) * (sl * sl + 1.0f));
            fg += (cl > 0);
        }
        {
            int cl = lc.y & 3, cp = pc.y & 3;
            float sl = le.y * s_invl[cl], sp = pe.y * s_invp[cp];
            float dot = sp * sl + ((cl == cp) ? 1.0f : 0.0f);
            acc += dot * rsqrtf((sp * sp + 1.0f) * (sl * sl + 1.0f));
            fg += (cl > 0);
        }
        {
            int cl = lc.z & 3, cp = pc.z & 3;
            float sl = le.z * s_invl[cl], sp = pe.z * s_invp[cp];
            float dot = sp * sl + ((cl == cp) ? 1.0f : 0.0f);
            acc += dot * rsqrtf((sp * sp + 1.0f) * (sl * sl + 1.0f));
            fg += (cl > 0);
        }
        {
            int cl = lc.w & 3, cp = pc.w & 3;
            float sl = le.w * s_invl[cl], sp = pe.w * s_invp[cp];
            float dot = sp * sl + ((cl == cp) ? 1.0f : 0.0f);
            acc += dot * rsqrtf((sp * sp + 1.0f) * (sl * sl + 1.0f));
            fg += (cl > 0);
        }
    }

    #pragma unroll
    for (int o = 16; o > 0; o >>= 1) {
        acc += __shfl_down_sync(0xffffffffu, acc, o);
        fg  += __shfl_down_sync(0xffffffffu, fg,  o);
    }
    int w = t >> 5;
    if ((t & 31) == 0) { wsum[w] = acc; wfg[w] = fg; }
    __syncthreads();

    if (t == 0) {
        float ssum = 0.0f; int sf = 0;
        #pragma unroll
        for (int k = 0; k < 8; ++k) { ssum += wsum[k]; sf += wfg[k]; }
        g_psum[b][blockIdx.x] = ssum;
        g_pfg [b][blockIdx.x] = sf;
        __threadfence();
        unsigned int old = atomicAdd(&g_tick, 1u);
        if (old == 63u) {                 // last of 64 blocks
            __threadfence();
            double loss = 0.0;
            for (int bb = 0; bb < NB; ++bb) {
                double s2 = 0.0; int f2 = 0;
                for (int k = 0; k < 16; ++k) { s2 += (double)g_psum[bb][k]; f2 += g_pfg[bb][k]; }
                float lb2 = 1.0f - (float)(s2 / 65536.0);
                if (f2 > 0) loss += (double)lb2;
            }
            float L = (float)(loss / (double)NB);
            if (isnan(L)) L = 0.0f;
            else if (isinf(L)) L = (L > 0.0f) ? 1.0f : 0.0f;
            out[0] = L;
            g_tick = 0u;
        }
    }
}

// ---------------------------------------------------------------------------
extern "C" void kernel_launch(void* const* d_in, const int* in_sizes, int n_in,
                              void* d_out, int out_size) {
    const float* pred;
    const int*   lab;
    if (n_in >= 2 && in_sizes[0] == NB*NPIX && in_sizes[1] == NB*NC*NPIX) {
        lab  = (const int*)d_in[0];
        pred = (const float*)d_in[1];
    } else {
        pred = (const float*)d_in[0];
        lab  = (const int*)d_in[1];
    }
    float* out = (float*)d_out;

    k1<<<NB*HH/4, 256>>>(pred, lab);      // 256 blocks — measured optimum
    k2<<<SRC*NB*WW/4, 256>>>();           // 512 blocks — measured optimum
    k3<<<dim3(16, NB), 256>>>(out);       // 64 blocks
    (void)out_size;
}

// round 17
// speedup vs baseline: 1.9958x; 1.0195x over previous
#include <cuda_runtime.h>
#include <math.h>

#define SRC 2      // 0 = lab, 1 = pred-argmax
#define NB  4
#define NC  3
#define HH  256
#define WW  256
#define NPIX (HH*WW)
#define LIMIT_F 331776.0f   // 576*576
#define NORM_EPS 1e-5f
#define DINF (1 << 20)

// Scratch (device globals). Transposed arrays: [src][b][j][i]
// g_pkT: (dm << 2) | label. dm = row-distance to nearest different-label pixel,
//        1..255, or 0 == "none in row" (reference BIG). rd = dm ? dm^2 : 1e9 exactly.
__device__ unsigned short g_pkT [SRC][NB][WW][HH];
__device__ float          g_edtT[SRC][NB][WW][HH];
__device__ unsigned int   g_cmax[SRC][NB][NC];
__device__ float          g_psum[NB][16];
__device__ int            g_pfg [NB][16];
__device__ unsigned int   g_tick;   // zero-init; reset by last K3 block

// ---------------------------------------------------------------------------
// K1: fused argmax + label pack + ballot row-pass EDT. 256 blocks x 512 thr;
// one block = 4 rows. Load work and ballot combos split across thread halves
// so each thread's serial chain is half as long as the 256-thread version.
__global__ void __launch_bounds__(512) k1(const float* __restrict__ pred,
                                          const int* __restrict__ lab) {
    int bx = blockIdx.x;            // 0..255
    int b  = bx >> 6;
    int i0 = (bx & 63) << 2;
    int t  = threadIdx.x;           // 0..511
    if (bx == 0 && t < SRC*NB*NC) ((unsigned int*)g_cmax)[t] = 0u;

    __shared__ unsigned char  s_lb[SRC][4][WW];
    __shared__ unsigned short s_pk[SRC][4][WW];
    __shared__ int            s_last[8][8], s_first[8][8];  // [comb][warp-of-j]

    // Phase A: threads 0..255 -> pred argmax (3 loads); 256..511 -> lab (1 load).
    if (t < 256) {
        int r  = t >> 6;
        int jj = (t & 63) << 2;
        size_t off = (size_t)b * NC * NPIX + (size_t)(i0 + r) * WW + jj;
        float4 p0 = *(const float4*)(pred + off);
        float4 p1 = *(const float4*)(pred + off + NPIX);
        float4 p2 = *(const float4*)(pred + off + 2*NPIX);
        uchar4 am;
        { int a=0; float v=p0.x; if (p1.x>v){v=p1.x;a=1;} if (p2.x>v){a=2;} am.x=(unsigned char)a; }
        { int a=0; float v=p0.y; if (p1.y>v){v=p1.y;a=1;} if (p2.y>v){a=2;} am.y=(unsigned char)a; }
        { int a=0; float v=p0.z; if (p1.z>v){v=p1.z;a=1;} if (p2.z>v){a=2;} am.z=(unsigned char)a; }
        { int a=0; float v=p0.w; if (p1.w>v){v=p1.w;a=1;} if (p2.w>v){a=2;} am.w=(unsigned char)a; }
        *(uchar4*)&s_lb[1][r][jj] = am;                    // jnp.argmax tie-break: strict >
    } else {
        int u  = t - 256;
        int r  = u >> 6;
        int jj = (u & 63) << 2;
        int4 lv = *(const int4*)(lab + (size_t)b * NPIX + (size_t)(i0 + r) * WW + jj);
        *(uchar4*)&s_lb[0][r][jj] = make_uchar4((unsigned char)lv.x, (unsigned char)lv.y,
                                                (unsigned char)lv.z, (unsigned char)lv.w);
    }
    __syncthreads();

    // Phase B: thread (j, grp) handles combos c = grp*4 .. grp*4+3.
    // combo c: src = c>>2, row = c&3. All lanes of a warp share grp -> ballots valid.
    int j = t & 255, grp = t >> 8;
    int lane = j & 31, w = j >> 5, base = j & ~31;
    unsigned mask_le = 0xffffffffu >> (31 - lane);
    int dl[4], dr[4];
    #pragma unroll
    for (int cc = 0; cc < 4; ++cc) {
        int c = grp * 4 + cc;
        const unsigned char* L = s_lb[c >> 2][c & 3];
        int bit = (j > 0) && (L[j] != L[j - 1]);
        unsigned bb = __ballot_sync(0xffffffffu, bit);
        unsigned bl = bb & mask_le;
        unsigned br = bb & ~mask_le;
        dl[cc] = bl ? (lane - (31 - __clz(bl)) + 1) : DINF;
        dr[cc] = br ? ((__ffs(br) - 1) - lane) : DINF;
        if (lane == 0) {
            s_last [c][w] = bb ? (base + 31 - __clz(bb)) : -1;
            s_first[c][w] = bb ? (base + __ffs(bb) - 1)  : -1;
        }
    }
    __syncthreads();

    // Phase C: cross-warp fallback (rare) + write packed (dm<<2)|lbl.
    #pragma unroll
    for (int cc = 0; cc < 4; ++cc) {
        int c = grp * 4 + cc;
        if (dl[cc] == DINF)
            for (int w2 = w - 1; w2 >= 0; --w2) {
                int k = s_last[c][w2];
                if (k >= 0) { dl[cc] = j - k + 1; break; }
            }
        if (dr[cc] == DINF)
            for (int w2 = w + 1; w2 < 8; ++w2) {
                int k = s_first[c][w2];
                if (k >= 0) { dr[cc] = k - j; break; }
            }
        int dm = min(dl[cc], dr[cc]);        // <=255 when found (row width 256)
        if (dm > 255) dm = 0;                // 0 == sentinel (no boundary in row)
        s_pk[c >> 2][c & 3][j] =
            (unsigned short)((dm << 2) | s_lb[c >> 2][c & 3][j]);
    }
    // No sync needed: each thread stores exactly the 4 s_pk values it just wrote.

    // Phase D: transposed ushort4 store — one 8B store per thread (src = grp).
    *(ushort4*)&g_pkT[grp][b][j][i0] =
        make_ushort4(s_pk[grp][0][j], s_pk[grp][1][j], s_pk[grp][2][j], s_pk[grp][3][j]);
}

// ---------------------------------------------------------------------------
// K2: column pass = ballot boundary init + bounded exact interior scan.
// Measured-best grid: 512 blocks x 256 threads, 4 columns per block. Unchanged.
__global__ void __launch_bounds__(256) k2() {
    int bx = blockIdx.x;            // 0..511
    int s  = bx >> 8;
    int b  = (bx >> 6) & 3;
    int j0 = (bx & 63) << 2;
    int i  = threadIdx.x;

    __shared__ unsigned char s_lb2[4][HH];
    __shared__ float         s_rd2[4][HH];
    __shared__ int           s_last[4][8], s_first[4][8];
    __shared__ unsigned int  smax[NC];
    if (i < NC) smax[i] = 0u;
    #pragma unroll
    for (int q = 0; q < 4; ++q) {
        unsigned short p = g_pkT[s][b][j0 + q][i];
        int dm = p >> 2;
        s_lb2[q][i] = (unsigned char)(p & 3);
        s_rd2[q][i] = dm ? (float)(dm * dm) : 1e9f;   // exact reconstruction
    }
    __syncthreads();

    int lane = i & 31, w = i >> 5, base = i & ~31;
    unsigned mask_le = 0xffffffffu >> (31 - lane);
    int dl[4], dr[4];
    #pragma unroll
    for (int q = 0; q < 4; ++q) {
        const unsigned char* L = s_lb2[q];
        int bit = (i > 0) && (L[i] != L[i - 1]);
        unsigned bb = __ballot_sync(0xffffffffu, bit);
        unsigned bl = bb & mask_le;
        unsigned br = bb & ~mask_le;
        dl[q] = bl ? (lane - (31 - __clz(bl)) + 1) : DINF;
        dr[q] = br ? ((__ffs(br) - 1) - lane) : DINF;
        if (lane == 0) {
            s_last [q][w] = bb ? (base + 31 - __clz(bb)) : -1;
            s_first[q][w] = bb ? (base + __ffs(bb) - 1)  : -1;
        }
    }
    __syncthreads();

    #pragma unroll
    for (int q = 0; q < 4; ++q) {
        if (dl[q] == DINF)
            for (int w2 = w - 1; w2 >= 0; --w2) {
                int k = s_last[q][w2];
                if (k >= 0) { dl[q] = i - k + 1; break; }
            }
        if (dr[q] == DINF)
            for (int w2 = w + 1; w2 < 8; ++w2) {
                int k = s_first[q][w2];
                if (k >= 0) { dr[q] = k - i; break; }
            }
        const float* R = s_rd2[q];
        float best = R[i];
        int dm = min(dl[q], dr[q]);
        if (dm < DINF) best = fminf(best, (float)(dm * dm));  // nearest different px, f=0
        // Exact interior scan: only same-run pixels (d < dl/dr) can win; past the
        // first different pixel every candidate has qd >= dl^2 >= best.
        int lim = min(dl[q], i + 1);
        for (int d = 1; d < lim; ++d) {
            float qd = (float)(d * d);
            if (qd >= best) break;
            float v = R[i - d] + qd;
            if (v < best) best = v;
        }
        lim = min(dr[q], HH - i);
        for (int d = 1; d < lim; ++d) {
            float qd = (float)(d * d);
            if (qd >= best) break;
            float v = R[i + d] + qd;
            if (v < best) best = v;
        }
        float e = sqrtf(best);
        g_edtT[s][b][j0 + q][i] = e;
        atomicMax(&smax[s_lb2[q][i]], __float_as_uint(e));  // e>=0: uint order == float
    }
    __syncthreads();
    if (i < NC) atomicMax(&g_cmax[s][b][i], smax[i]);
}

// ---------------------------------------------------------------------------
// K3: per-pixel cosine similarity + deterministic reduce + ticketed finish.
// 64 blocks (spread matters: MUFU rsqrt throughput — R15 post-mortem). Unchanged.
__global__ void __launch_bounds__(256) k3(float* __restrict__ out) {
    int b = blockIdx.y;
    int t = threadIdx.x;
    __shared__ float s_invl[NC], s_invp[NC];
    __shared__ float wsum[8];
    __shared__ int   wfg[8];
    if (t < NC)
        s_invl[t] = 1.0f / (fminf(__uint_as_float(g_cmax[0][b][t]), LIMIT_F) + NORM_EPS);
    else if (t < 2*NC)
        s_invp[t - NC] = 1.0f / (fminf(__uint_as_float(g_cmax[1][b][t - NC]), LIMIT_F) + NORM_EPS);
    __syncthreads();

    const ushort4* Lc = (const ushort4*)g_pkT[0][b];
    const ushort4* Pc = (const ushort4*)g_pkT[1][b];
    const float4*  Le = (const float4*)g_edtT[0][b];
    const float4*  Pe = (const float4*)g_edtT[1][b];

    int base = blockIdx.x * 1024;
    float acc = 0.0f; int fg = 0;
    #pragma unroll
    for (int u = 0; u < 4; ++u) {
        int v = base + u * 256 + t;
        ushort4 lc = Lc[v], pc = Pc[v];
        float4  le = Le[v], pe = Pe[v];
        {
            int cl = lc.x & 3, cp = pc.x & 3;
            float sl = le.x * s_invl[cl], sp = pe.x * s_invp[cp];
            float dot = sp * sl + ((cl == cp) ? 1.0f : 0.0f);
            acc += dot * rsqrtf((sp * sp + 1.0f) * (sl * sl + 1.0f));
            fg += (cl > 0);
        }
        {
            int cl = lc.y & 3, cp = pc.y & 3;
            float sl = le.y * s_invl[cl], sp = pe.y * s_invp[cp];
            float dot = sp * sl + ((cl == cp) ? 1.0f : 0.0f);
            acc += dot * rsqrtf((sp * sp + 1.0f) * (sl * sl + 1.0f));
            fg += (cl > 0);
        }
        {
            int cl = lc.z & 3, cp = pc.z & 3;
            float sl = le.z * s_invl[cl], sp = pe.z * s_invp[cp];
            float dot = sp * sl + ((cl == cp) ? 1.0f : 0.0f);
            acc += dot * rsqrtf((sp * sp + 1.0f) * (sl * sl + 1.0f));
            fg += (cl > 0);
        }
        {
            int cl = lc.w & 3, cp = pc.w & 3;
            float sl = le.w * s_invl[cl], sp = pe.w * s_invp[cp];
            float dot = sp * sl + ((cl == cp) ? 1.0f : 0.0f);
            acc += dot * rsqrtf((sp * sp + 1.0f) * (sl * sl + 1.0f));
            fg += (cl > 0);
        }
    }

    #pragma unroll
    for (int o = 16; o > 0; o >>= 1) {
        acc += __shfl_down_sync(0xffffffffu, acc, o);
        fg  += __shfl_down_sync(0xffffffffu, fg,  o);
    }
    int w = t >> 5;
    if ((t & 31) == 0) { wsum[w] = acc; wfg[w] = fg; }
    __syncthreads();

    if (t == 0) {
        float ssum = 0.0f; int sf = 0;
        #pragma unroll
        for (int k = 0; k < 8; ++k) { ssum += wsum[k]; sf += wfg[k]; }
        g_psum[b][blockIdx.x] = ssum;
        g_pfg [b][blockIdx.x] = sf;
        __threadfence();
        unsigned int old = atomicAdd(&g_tick, 1u);
        if (old == 63u) {                 // last of 64 blocks
            __threadfence();
            double loss = 0.0;
            for (int bb = 0; bb < NB; ++bb) {
                double s2 = 0.0; int f2 = 0;
                for (int k = 0; k < 16; ++k) { s2 += (double)g_psum[bb][k]; f2 += g_pfg[bb][k]; }
                float lb2 = 1.0f - (float)(s2 / 65536.0);
                if (f2 > 0) loss += (double)lb2;
            }
            float L = (float)(loss / (double)NB);
            if (isnan(L)) L = 0.0f;
            else if (isinf(L)) L = (L > 0.0f) ? 1.0f : 0.0f;
            out[0] = L;
            g_tick = 0u;
        }
    }
}

// ---------------------------------------------------------------------------
extern "C" void kernel_launch(void* const* d_in, const int* in_sizes, int n_in,
                              void* d_out, int out_size) {
    const float* pred;
    const int*   lab;
    if (n_in >= 2 && in_sizes[0] == NB*NPIX && in_sizes[1] == NB*NC*NPIX) {
        lab  = (const int*)d_in[0];
        pred = (const float*)d_in[1];
    } else {
        pred = (const float*)d_in[0];
        lab  = (const int*)d_in[1];
    }
    float* out = (float*)d_out;

    k1<<<NB*HH/4, 512>>>(pred, lab);      // 256 blocks x 512 thr
    k2<<<SRC*NB*WW/4, 256>>>();           // 512 blocks — measured optimum
    k3<<<dim3(16, NB), 256>>>(out);       // 64 blocks
    (void)out_size;
}